// round 11
// baseline (speedup 1.0000x reference)
#include <cuda_runtime.h>

// ---------------------------------------------------------------------------
// DecoderBlock: conv3x3(64->3) + bias + tanh  -> ll [16,3,128,128]
// then two fused inverse Haar levels          -> out [16,3,512,512]
//
// R11: R10 (split-K + shuffle halo) with register diet:
//      raw-float4 double buffers, halo expanded at use, per-o weight loads,
//      __launch_bounds__(128,8) -> 8 CTAs/SM target.
// ---------------------------------------------------------------------------

#define NB   16
#define CIN  64
#define KSPLIT 2
#define KCH  (CIN / KSPLIT)     // 32 channels per CTA
#define HH   128
#define WW   128
#define HW   (HH * WW)

// partial conv sums: [kslice][b][o][h][w] = 2 * 3 MB
__device__ float g_part[KSPLIT * NB * 3 * HW];

__device__ __forceinline__ void stcs4(float* p, float4 v) {
    asm volatile("st.global.cs.v4.f32 [%0], {%1,%2,%3,%4};"
                 :: "l"(p), "f"(v.x), "f"(v.y), "f"(v.z), "f"(v.w));
}

// ---------------------------------------------------------------------------
// Kernel A: streaming conv 3x3 pad1, split-K partial sums.
// Thread = 1 row x 4 cols x 3 outch. CTA (32,4); warp = one output row,
// lanes = contiguous col quads; halo via shfl at use time.
// Grid (32,16,2) = 1024 CTAs.
// ---------------------------------------------------------------------------
__global__ __launch_bounds__(128, 8) void conv_part_kernel(
    const float* __restrict__ fused,
    const float* __restrict__ conv_w)
{
    __shared__ float s_w[KCH * 36];           // 4608 B, [c][o*12 + t]

    const int tx  = threadIdx.x;              // lane 0..31 -> cols 4tx..4tx+3
    const int ty  = threadIdx.y;              // 0..3
    const int tid = ty * 32 + tx;
    const int b   = blockIdx.y;
    const int ks  = blockIdx.z;               // k-slice 0/1
    const int kbase = ks * KCH;
    const int gy  = blockIdx.x * 4 + ty;      // output row 0..127

    // stage weights: s_w[c*36 + o*12 + t] (src layout [o][cin][3][3])
    for (int i = tid; i < KCH * 27; i += 128) {
        int c = i / 27, r = i % 27;
        s_w[c * 36 + (r / 9) * 12 + (r % 9)] =
            conv_w[(r / 9) * (CIN * 9) + (kbase + c) * 9 + (r % 9)];
    }
    __syncthreads();

    const bool vtop = (gy > 0);
    const bool vbot = (gy < HH - 1);
    const bool vl   = (tx > 0);
    const bool vr   = (tx < 31);
    const float* p0 = fused + (long)b * CIN * HW + (long)kbase * HW
                            + (gy - 1) * WW + 4 * tx;

    // raw per-channel patch: 3 rows x float4 (cols 4tx..4tx+3)
    float4 m0[3], m1[3];

    auto loadraw = [&](int c, float4 (&m)[3]) {
        const bool rv[3] = { vtop, true, vbot };
#pragma unroll
        for (int k = 0; k < 3; k++) {
            m[k] = make_float4(0.f, 0.f, 0.f, 0.f);
            if (rv[k])
                m[k] = __ldg(reinterpret_cast<const float4*>(p0 + c * HW + k * WW));
        }
    };

    float acc[3][4];
#pragma unroll
    for (int o = 0; o < 3; o++)
#pragma unroll
        for (int q = 0; q < 4; q++) acc[o][q] = 0.0f;

    auto compute = [&](int c, float4 (&m)[3]) {
        // halo via warp shuffle (all lanes participate; edges select 0)
        float lft[3], rgt[3];
#pragma unroll
        for (int k = 0; k < 3; k++) {
            float l = __shfl_up_sync(0xffffffffu, m[k].w, 1);
            float r = __shfl_down_sync(0xffffffffu, m[k].x, 1);
            lft[k] = vl ? l : 0.0f;
            rgt[k] = vr ? r : 0.0f;
        }
#pragma unroll
        for (int o = 0; o < 3; o++) {
            const float* wb = &s_w[c * 36 + o * 12];
            float4 wa = *reinterpret_cast<const float4*>(wb);
            float4 wm = *reinterpret_cast<const float4*>(wb + 4);
            float4 wz = *reinterpret_cast<const float4*>(wb + 8);
            const float w[9] = { wa.x, wa.y, wa.z, wa.w,
                                 wm.x, wm.y, wm.z, wm.w, wz.x };
#pragma unroll
            for (int ky = 0; ky < 3; ky++) {
                const float x0 = lft[ky];
                const float x1 = m[ky].x, x2 = m[ky].y,
                            x3 = m[ky].z, x4 = m[ky].w;
                const float x5 = rgt[ky];
                const float wA = w[ky * 3 + 0];
                const float wB = w[ky * 3 + 1];
                const float wC = w[ky * 3 + 2];
                acc[o][0] += wA * x0 + 0.0f;   // kept simple: 3 FMA per q below
                acc[o][0] -= wA * x0;          // (see expanded form)
                // expanded accumulation (q = 0..3), 9 FMAs per row-triple
                acc[o][0] += wA * x0; acc[o][0] += wB * x1; acc[o][0] += wC * x2;
                acc[o][1] += wA * x1; acc[o][1] += wB * x2; acc[o][1] += wC * x3;
                acc[o][2] += wA * x2; acc[o][2] += wB * x3; acc[o][2] += wC * x4;
                acc[o][3] += wA * x3; acc[o][3] += wB * x4; acc[o][3] += wC * x5;
            }
        }
    };

    loadraw(0, m0);
#pragma unroll 1
    for (int c = 0; c < KCH; c += 2) {
        loadraw(c + 1, m1);
        compute(c, m0);
        if (c + 2 < KCH) loadraw(c + 2, m0);
        compute(c + 1, m1);
    }

    // raw partial sums, one float4 per out channel
    float* pp = &g_part[(long)ks * NB * 3 * HW];
#pragma unroll
    for (int o = 0; o < 3; o++) {
        float4 v;
        v.x = acc[o][0]; v.y = acc[o][1]; v.z = acc[o][2]; v.w = acc[o][3];
        *reinterpret_cast<float4*>(
            &pp[((b * 3 + o) * HH + gy) * WW + 4 * tx]) = v;
    }
}

// ---------------------------------------------------------------------------
// Kernel B: combine(partials)+bias+tanh fused with double inverse Haar.
// ---------------------------------------------------------------------------
__global__ __launch_bounds__(256) void iwt2_kernel(
    const float* __restrict__ hf1,
    const float* __restrict__ hf2,
    const float* __restrict__ conv_b,
    float* __restrict__ out)
{
    const int w0 = threadIdx.x;                        // 0..127
    const int h0 = blockIdx.x * 2 + threadIdx.y;       // 0..127
    const int z  = blockIdx.y;                         // b*3 + c
    const int b  = z / 3;
    const int c  = z - b * 3;

    const int llidx = (z * HH + h0) * WW + w0;
    const float a = tanhf(g_part[llidx] + g_part[NB * 3 * HW + llidx]
                          + __ldg(&conv_b[c]));

    const int hf2base = ((b * 9 + 3 * c) * HH + h0) * WW + w0;
    const float lh = 2.0f * __ldg(&hf2[hf2base            ]) - 1.0f;
    const float hl = 2.0f * __ldg(&hf2[hf2base + HH * WW  ]) - 1.0f;
    const float hh = 2.0f * __ldg(&hf2[hf2base + 2*HH*WW  ]) - 1.0f;

    float cur[2][2];
    cur[0][0] = 0.5f * (a - lh - hl + hh);
    cur[0][1] = 0.5f * (a - lh + hl - hh);
    cur[1][0] = 0.5f * (a + lh - hl - hh);
    cur[1][1] = 0.5f * (a + lh + hl + hh);

    const int h1 = 2 * h0;
    const int w1 = 2 * w0;
    float2 v[3][2];
#pragma unroll
    for (int k = 0; k < 3; k++) {
#pragma unroll
        for (int p0 = 0; p0 < 2; p0++) {
            const float2* ptr = reinterpret_cast<const float2*>(
                &hf1[((b * 9 + 3 * c + k) * 256 + (h1 + p0)) * 256 + w1]);
            v[k][p0] = __ldg(ptr);
        }
    }

    float o16[4][4];
#pragma unroll
    for (int p0 = 0; p0 < 2; p0++) {
#pragma unroll
        for (int q0 = 0; q0 < 2; q0++) {
            const float a2  = cur[p0][q0];
            const float lh1 = 2.0f * (q0 == 0 ? v[0][p0].x : v[0][p0].y) - 1.0f;
            const float hl1 = 2.0f * (q0 == 0 ? v[1][p0].x : v[1][p0].y) - 1.0f;
            const float hh1 = 2.0f * (q0 == 0 ? v[2][p0].x : v[2][p0].y) - 1.0f;
            o16[2 * p0 + 0][2 * q0 + 0] = 0.5f * (a2 - lh1 - hl1 + hh1);
            o16[2 * p0 + 0][2 * q0 + 1] = 0.5f * (a2 - lh1 + hl1 - hh1);
            o16[2 * p0 + 1][2 * q0 + 0] = 0.5f * (a2 + lh1 - hl1 - hh1);
            o16[2 * p0 + 1][2 * q0 + 1] = 0.5f * (a2 + lh1 + hl1 + hh1);
        }
    }

#pragma unroll
    for (int r = 0; r < 4; r++) {
        float4 row;
        row.x = o16[r][0]; row.y = o16[r][1];
        row.z = o16[r][2]; row.w = o16[r][3];
        stcs4(&out[((long)z * 512 + (4 * h0 + r)) * 512 + 4 * w0], row);
    }
}

// ---------------------------------------------------------------------------
extern "C" void kernel_launch(void* const* d_in, const int* in_sizes, int n_in,
                              void* d_out, int out_size)
{
    const float* fused  = (const float*)d_in[0];
    const float* hf1    = (const float*)d_in[1];
    const float* hf2    = (const float*)d_in[2];
    const float* conv_w = (const float*)d_in[3];
    const float* conv_b = (const float*)d_in[4];
    float* out = (float*)d_out;

    dim3 cb(32, 4);
    dim3 cg(HH / 4, NB, KSPLIT);            // (32,16,2) = 1024 CTAs
    conv_part_kernel<<<cg, cb>>>(fused, conv_w);

    dim3 ib(128, 2);
    dim3 ig(HH / 2, NB * 3);                // (64,48) = 3072 CTAs
    iwt2_kernel<<<ig, ib>>>(hf1, hf2, conv_b, out);
}

// round 14
// speedup vs baseline: 1.0689x; 1.0689x over previous
#include <cuda_runtime.h>

// ---------------------------------------------------------------------------
// DecoderBlock: conv3x3(64->3) + bias + tanh  -> ll [16,3,128,128]
// then two fused inverse Haar levels          -> out [16,3,512,512]
//
// R12: R11 cleaned (junk FMAs removed). Split-K conv, shuffle halo,
//      raw-float4 double buffers, per-o weight loads, 8 CTAs/SM target
//      -> single wave. iwt2: streaming loads (.cs) + streaming stores.
// ---------------------------------------------------------------------------

#define NB   16
#define CIN  64
#define KSPLIT 2
#define KCH  (CIN / KSPLIT)     // 32 channels per CTA
#define HH   128
#define WW   128
#define HW   (HH * WW)

// partial conv sums: [kslice][b][o][h][w] = 2 * 3 MB
__device__ float g_part[KSPLIT * NB * 3 * HW];

__device__ __forceinline__ void stcs4(float* p, float4 v) {
    asm volatile("st.global.cs.v4.f32 [%0], {%1,%2,%3,%4};"
                 :: "l"(p), "f"(v.x), "f"(v.y), "f"(v.z), "f"(v.w));
}

// ---------------------------------------------------------------------------
// Kernel A: streaming conv 3x3 pad1, split-K partial sums.
// Thread = 1 row x 4 cols x 3 outch. CTA (32,4); warp = one output row,
// lanes = contiguous col quads; halo via shfl at use time.
// Grid (32,16,2) = 1024 CTAs; at 8 CTAs/SM this is a single wave.
// ---------------------------------------------------------------------------
__global__ __launch_bounds__(128, 8) void conv_part_kernel(
    const float* __restrict__ fused,
    const float* __restrict__ conv_w)
{
    __shared__ float s_w[KCH * 36];           // 4608 B, [c][o*12 + t]

    const int tx  = threadIdx.x;              // lane 0..31 -> cols 4tx..4tx+3
    const int ty  = threadIdx.y;              // 0..3
    const int tid = ty * 32 + tx;
    const int b   = blockIdx.y;
    const int ks  = blockIdx.z;               // k-slice 0/1
    const int kbase = ks * KCH;
    const int gy  = blockIdx.x * 4 + ty;      // output row 0..127

    // stage weights: s_w[c*36 + o*12 + t] (src layout [o][cin][3][3])
    for (int i = tid; i < KCH * 27; i += 128) {
        int c = i / 27, r = i % 27;
        s_w[c * 36 + (r / 9) * 12 + (r % 9)] =
            conv_w[(r / 9) * (CIN * 9) + (kbase + c) * 9 + (r % 9)];
    }
    __syncthreads();

    const bool vtop = (gy > 0);
    const bool vbot = (gy < HH - 1);
    const bool vl   = (tx > 0);
    const bool vr   = (tx < 31);
    const float* p0 = fused + (long)b * CIN * HW + (long)kbase * HW
                            + (gy - 1) * WW + 4 * tx;

    // raw per-channel patch: 3 rows x float4 (cols 4tx..4tx+3)
    float4 m0[3], m1[3];

    auto loadraw = [&](int c, float4 (&m)[3]) {
        const bool rv[3] = { vtop, true, vbot };
#pragma unroll
        for (int k = 0; k < 3; k++) {
            m[k] = make_float4(0.f, 0.f, 0.f, 0.f);
            if (rv[k])
                m[k] = __ldg(reinterpret_cast<const float4*>(p0 + c * HW + k * WW));
        }
    };

    float acc[3][4];
#pragma unroll
    for (int o = 0; o < 3; o++)
#pragma unroll
        for (int q = 0; q < 4; q++) acc[o][q] = 0.0f;

    auto compute = [&](int c, float4 (&m)[3]) {
        // halo via warp shuffle (all lanes participate; edges select 0)
        float lft[3], rgt[3];
#pragma unroll
        for (int k = 0; k < 3; k++) {
            float l = __shfl_up_sync(0xffffffffu, m[k].w, 1);
            float r = __shfl_down_sync(0xffffffffu, m[k].x, 1);
            lft[k] = vl ? l : 0.0f;
            rgt[k] = vr ? r : 0.0f;
        }
#pragma unroll
        for (int o = 0; o < 3; o++) {
            const float* wb = &s_w[c * 36 + o * 12];
            float4 wa = *reinterpret_cast<const float4*>(wb);
            float4 wm = *reinterpret_cast<const float4*>(wb + 4);
            float4 wz = *reinterpret_cast<const float4*>(wb + 8);
            const float w[9] = { wa.x, wa.y, wa.z, wa.w,
                                 wm.x, wm.y, wm.z, wm.w, wz.x };
#pragma unroll
            for (int ky = 0; ky < 3; ky++) {
                const float x0 = lft[ky];
                const float x1 = m[ky].x, x2 = m[ky].y,
                            x3 = m[ky].z, x4 = m[ky].w;
                const float x5 = rgt[ky];
                const float wA = w[ky * 3 + 0];
                const float wB = w[ky * 3 + 1];
                const float wC = w[ky * 3 + 2];
                acc[o][0] += wA * x0; acc[o][0] += wB * x1; acc[o][0] += wC * x2;
                acc[o][1] += wA * x1; acc[o][1] += wB * x2; acc[o][1] += wC * x3;
                acc[o][2] += wA * x2; acc[o][2] += wB * x3; acc[o][2] += wC * x4;
                acc[o][3] += wA * x3; acc[o][3] += wB * x4; acc[o][3] += wC * x5;
            }
        }
    };

    loadraw(0, m0);
#pragma unroll 1
    for (int c = 0; c < KCH; c += 2) {
        loadraw(c + 1, m1);
        compute(c, m0);
        if (c + 2 < KCH) loadraw(c + 2, m0);
        compute(c + 1, m1);
    }

    // raw partial sums, one float4 per out channel
    float* pp = &g_part[(long)ks * NB * 3 * HW];
#pragma unroll
    for (int o = 0; o < 3; o++) {
        float4 v;
        v.x = acc[o][0]; v.y = acc[o][1]; v.z = acc[o][2]; v.w = acc[o][3];
        *reinterpret_cast<float4*>(
            &pp[((b * 3 + o) * HH + gy) * WW + 4 * tx]) = v;
    }
}

// ---------------------------------------------------------------------------
// Kernel B: combine(partials)+bias+tanh fused with double inverse Haar.
// Read-once streams (hf1, hf2) use .cs loads; output uses .cs stores.
// ---------------------------------------------------------------------------
__global__ __launch_bounds__(256) void iwt2_kernel(
    const float* __restrict__ hf1,
    const float* __restrict__ hf2,
    const float* __restrict__ conv_b,
    float* __restrict__ out)
{
    const int w0 = threadIdx.x;                        // 0..127
    const int h0 = blockIdx.x * 2 + threadIdx.y;       // 0..127
    const int z  = blockIdx.y;                         // b*3 + c
    const int b  = z / 3;
    const int c  = z - b * 3;

    const int llidx = (z * HH + h0) * WW + w0;
    const float a = tanhf(g_part[llidx] + g_part[NB * 3 * HW + llidx]
                          + __ldg(&conv_b[c]));

    const int hf2base = ((b * 9 + 3 * c) * HH + h0) * WW + w0;
    const float lh = 2.0f * __ldcs(&hf2[hf2base            ]) - 1.0f;
    const float hl = 2.0f * __ldcs(&hf2[hf2base + HH * WW  ]) - 1.0f;
    const float hh = 2.0f * __ldcs(&hf2[hf2base + 2*HH*WW  ]) - 1.0f;

    float cur[2][2];
    cur[0][0] = 0.5f * (a - lh - hl + hh);
    cur[0][1] = 0.5f * (a - lh + hl - hh);
    cur[1][0] = 0.5f * (a + lh - hl - hh);
    cur[1][1] = 0.5f * (a + lh + hl + hh);

    const int h1 = 2 * h0;
    const int w1 = 2 * w0;
    float2 v[3][2];
#pragma unroll
    for (int k = 0; k < 3; k++) {
#pragma unroll
        for (int p0 = 0; p0 < 2; p0++) {
            const float2* ptr = reinterpret_cast<const float2*>(
                &hf1[((b * 9 + 3 * c + k) * 256 + (h1 + p0)) * 256 + w1]);
            v[k][p0] = __ldcs(ptr);
        }
    }

    float o16[4][4];
#pragma unroll
    for (int p0 = 0; p0 < 2; p0++) {
#pragma unroll
        for (int q0 = 0; q0 < 2; q0++) {
            const float a2  = cur[p0][q0];
            const float lh1 = 2.0f * (q0 == 0 ? v[0][p0].x : v[0][p0].y) - 1.0f;
            const float hl1 = 2.0f * (q0 == 0 ? v[1][p0].x : v[1][p0].y) - 1.0f;
            const float hh1 = 2.0f * (q0 == 0 ? v[2][p0].x : v[2][p0].y) - 1.0f;
            o16[2 * p0 + 0][2 * q0 + 0] = 0.5f * (a2 - lh1 - hl1 + hh1);
            o16[2 * p0 + 0][2 * q0 + 1] = 0.5f * (a2 - lh1 + hl1 - hh1);
            o16[2 * p0 + 1][2 * q0 + 0] = 0.5f * (a2 + lh1 - hl1 - hh1);
            o16[2 * p0 + 1][2 * q0 + 1] = 0.5f * (a2 + lh1 + hl1 + hh1);
        }
    }

#pragma unroll
    for (int r = 0; r < 4; r++) {
        float4 row;
        row.x = o16[r][0]; row.y = o16[r][1];
        row.z = o16[r][2]; row.w = o16[r][3];
        stcs4(&out[((long)z * 512 + (4 * h0 + r)) * 512 + 4 * w0], row);
    }
}

// ---------------------------------------------------------------------------
extern "C" void kernel_launch(void* const* d_in, const int* in_sizes, int n_in,
                              void* d_out, int out_size)
{
    const float* fused  = (const float*)d_in[0];
    const float* hf1    = (const float*)d_in[1];
    const float* hf2    = (const float*)d_in[2];
    const float* conv_w = (const float*)d_in[3];
    const float* conv_b = (const float*)d_in[4];
    float* out = (float*)d_out;

    dim3 cb(32, 4);
    dim3 cg(HH / 4, NB, KSPLIT);            // (32,16,2) = 1024 CTAs
    conv_part_kernel<<<cg, cb>>>(fused, conv_w);

    dim3 ib(128, 2);
    dim3 ig(HH / 2, NB * 3);                // (64,48) = 3072 CTAs
    iwt2_kernel<<<ig, ib>>>(hf1, hf2, conv_b, out);
}

// round 17
// speedup vs baseline: 1.0711x; 1.0021x over previous
#include <cuda_runtime.h>

// ---------------------------------------------------------------------------
// DecoderBlock: conv3x3(64->3) + bias + tanh  -> ll [16,3,128,128]
// then two fused inverse Haar levels          -> out [16,3,512,512]
//
// R15: conv identical to R12/R14 (best: ~30.4us).
//      iwt2 rewritten with folded-scale Haar butterflies:
//      level-1 rescale X' = .5v - .25, level-2 L = v - .5, all syntheses
//      become 8-add 2x2 butterflies. ~40 fewer flops/thread.
// ---------------------------------------------------------------------------

#define NB   16
#define CIN  64
#define KSPLIT 2
#define KCH  (CIN / KSPLIT)     // 32 channels per CTA
#define HH   128
#define WW   128
#define HW   (HH * WW)

// partial conv sums: [kslice][b][o][h][w] = 2 * 3 MB
__device__ float g_part[KSPLIT * NB * 3 * HW];

__device__ __forceinline__ void stcs4(float* p, float4 v) {
    asm volatile("st.global.cs.v4.f32 [%0], {%1,%2,%3,%4};"
                 :: "l"(p), "f"(v.x), "f"(v.y), "f"(v.z), "f"(v.w));
}

// ---------------------------------------------------------------------------
// Kernel A: streaming conv 3x3 pad1, split-K partial sums. (unchanged R12)
// ---------------------------------------------------------------------------
__global__ __launch_bounds__(128, 8) void conv_part_kernel(
    const float* __restrict__ fused,
    const float* __restrict__ conv_w)
{
    __shared__ float s_w[KCH * 36];           // 4608 B, [c][o*12 + t]

    const int tx  = threadIdx.x;              // lane 0..31 -> cols 4tx..4tx+3
    const int ty  = threadIdx.y;              // 0..3
    const int tid = ty * 32 + tx;
    const int b   = blockIdx.y;
    const int ks  = blockIdx.z;               // k-slice 0/1
    const int kbase = ks * KCH;
    const int gy  = blockIdx.x * 4 + ty;      // output row 0..127

    for (int i = tid; i < KCH * 27; i += 128) {
        int c = i / 27, r = i % 27;
        s_w[c * 36 + (r / 9) * 12 + (r % 9)] =
            conv_w[(r / 9) * (CIN * 9) + (kbase + c) * 9 + (r % 9)];
    }
    __syncthreads();

    const bool vtop = (gy > 0);
    const bool vbot = (gy < HH - 1);
    const bool vl   = (tx > 0);
    const bool vr   = (tx < 31);
    const float* p0 = fused + (long)b * CIN * HW + (long)kbase * HW
                            + (gy - 1) * WW + 4 * tx;

    float4 m0[3], m1[3];

    auto loadraw = [&](int c, float4 (&m)[3]) {
        const bool rv[3] = { vtop, true, vbot };
#pragma unroll
        for (int k = 0; k < 3; k++) {
            m[k] = make_float4(0.f, 0.f, 0.f, 0.f);
            if (rv[k])
                m[k] = __ldg(reinterpret_cast<const float4*>(p0 + c * HW + k * WW));
        }
    };

    float acc[3][4];
#pragma unroll
    for (int o = 0; o < 3; o++)
#pragma unroll
        for (int q = 0; q < 4; q++) acc[o][q] = 0.0f;

    auto compute = [&](int c, float4 (&m)[3]) {
        float lft[3], rgt[3];
#pragma unroll
        for (int k = 0; k < 3; k++) {
            float l = __shfl_up_sync(0xffffffffu, m[k].w, 1);
            float r = __shfl_down_sync(0xffffffffu, m[k].x, 1);
            lft[k] = vl ? l : 0.0f;
            rgt[k] = vr ? r : 0.0f;
        }
#pragma unroll
        for (int o = 0; o < 3; o++) {
            const float* wb = &s_w[c * 36 + o * 12];
            float4 wa = *reinterpret_cast<const float4*>(wb);
            float4 wm = *reinterpret_cast<const float4*>(wb + 4);
            float4 wz = *reinterpret_cast<const float4*>(wb + 8);
            const float w[9] = { wa.x, wa.y, wa.z, wa.w,
                                 wm.x, wm.y, wm.z, wm.w, wz.x };
#pragma unroll
            for (int ky = 0; ky < 3; ky++) {
                const float x0 = lft[ky];
                const float x1 = m[ky].x, x2 = m[ky].y,
                            x3 = m[ky].z, x4 = m[ky].w;
                const float x5 = rgt[ky];
                const float wA = w[ky * 3 + 0];
                const float wB = w[ky * 3 + 1];
                const float wC = w[ky * 3 + 2];
                acc[o][0] += wA * x0; acc[o][0] += wB * x1; acc[o][0] += wC * x2;
                acc[o][1] += wA * x1; acc[o][1] += wB * x2; acc[o][1] += wC * x3;
                acc[o][2] += wA * x2; acc[o][2] += wB * x3; acc[o][2] += wC * x4;
                acc[o][3] += wA * x3; acc[o][3] += wB * x4; acc[o][3] += wC * x5;
            }
        }
    };

    loadraw(0, m0);
#pragma unroll 1
    for (int c = 0; c < KCH; c += 2) {
        loadraw(c + 1, m1);
        compute(c, m0);
        if (c + 2 < KCH) loadraw(c + 2, m0);
        compute(c + 1, m1);
    }

    float* pp = &g_part[(long)ks * NB * 3 * HW];
#pragma unroll
    for (int o = 0; o < 3; o++) {
        float4 v;
        v.x = acc[o][0]; v.y = acc[o][1]; v.z = acc[o][2]; v.w = acc[o][3];
        *reinterpret_cast<float4*>(
            &pp[((b * 3 + o) * HH + gy) * WW + 4 * tx]) = v;
    }
}

// ---------------------------------------------------------------------------
// Kernel B: combine(partials)+bias+tanh fused with double inverse Haar,
// folded-scale butterfly form.
//   level-1: A0 = .25*a, X' = .5*v - .25  (X in {lh,hl,hh})
//            m0=A0-Lh m1=A0+Lh n0=Hl-Hh n1=Hl+Hh
//            curq = {m0-n0, m0+n0, m1-n1, m1+n1}  (== .5 * true level-1 out)
//   level-2: A = cur', L = v - .5 per hf1 value
//            mm0=A-L mm1=A+L nn0=H-G nn1=H+G -> 4 outputs by +-.
// ---------------------------------------------------------------------------
__global__ __launch_bounds__(256) void iwt2_kernel(
    const float* __restrict__ hf1,
    const float* __restrict__ hf2,
    const float* __restrict__ conv_b,
    float* __restrict__ out)
{
    const int w0 = threadIdx.x;                        // 0..127
    const int h0 = blockIdx.x * 2 + threadIdx.y;       // 0..127
    const int z  = blockIdx.y;                         // b*3 + c
    const int b  = z / 3;
    const int c  = z - b * 3;

    const int llidx = (z * HH + h0) * WW + w0;
    const float a = tanhf(g_part[llidx] + g_part[NB * 3 * HW + llidx]
                          + __ldg(&conv_b[c]));

    // level-1, folded scale (.25)
    const int hf2base = ((b * 9 + 3 * c) * HH + h0) * WW + w0;
    const float A0 = 0.25f * a;
    const float Lh = 0.5f * __ldcs(&hf2[hf2base            ]) - 0.25f;
    const float Hl = 0.5f * __ldcs(&hf2[hf2base + HH * WW  ]) - 0.25f;
    const float Hh = 0.5f * __ldcs(&hf2[hf2base + 2*HH*WW  ]) - 0.25f;

    const float m0 = A0 - Lh, m1 = A0 + Lh;
    const float n0 = Hl - Hh, n1 = Hl + Hh;
    float cur[2][2];                 // == .5 * level-1 output (= A for lvl 2)
    cur[0][0] = m0 - n0;
    cur[0][1] = m0 + n0;
    cur[1][0] = m1 - n1;
    cur[1][1] = m1 + n1;

    // level-2 hf1 (256x256 planes): 3 channels x 2 rows, float2 along cols
    const int h1 = 2 * h0;
    const int w1 = 2 * w0;
    float2 v[3][2];
#pragma unroll
    for (int k = 0; k < 3; k++) {
#pragma unroll
        for (int p0 = 0; p0 < 2; p0++) {
            const float2* ptr = reinterpret_cast<const float2*>(
                &hf1[((b * 9 + 3 * c + k) * 256 + (h1 + p0)) * 256 + w1]);
            v[k][p0] = __ldcs(ptr);
        }
    }

    float o16[4][4];
#pragma unroll
    for (int p0 = 0; p0 < 2; p0++) {
#pragma unroll
        for (int q0 = 0; q0 < 2; q0++) {
            const float A = cur[p0][q0];
            const float L = (q0 == 0 ? v[0][p0].x : v[0][p0].y) - 0.5f;
            const float H = (q0 == 0 ? v[1][p0].x : v[1][p0].y) - 0.5f;
            const float G = (q0 == 0 ? v[2][p0].x : v[2][p0].y) - 0.5f;
            const float mm0 = A - L, mm1 = A + L;
            const float nn0 = H - G, nn1 = H + G;
            o16[2 * p0 + 0][2 * q0 + 0] = mm0 - nn0;
            o16[2 * p0 + 0][2 * q0 + 1] = mm0 + nn0;
            o16[2 * p0 + 1][2 * q0 + 0] = mm1 - nn1;
            o16[2 * p0 + 1][2 * q0 + 1] = mm1 + nn1;
        }
    }

#pragma unroll
    for (int r = 0; r < 4; r++) {
        float4 row;
        row.x = o16[r][0]; row.y = o16[r][1];
        row.z = o16[r][2]; row.w = o16[r][3];
        stcs4(&out[((long)z * 512 + (4 * h0 + r)) * 512 + 4 * w0], row);
    }
}

// ---------------------------------------------------------------------------
extern "C" void kernel_launch(void* const* d_in, const int* in_sizes, int n_in,
                              void* d_out, int out_size)
{
    const float* fused  = (const float*)d_in[0];
    const float* hf1    = (const float*)d_in[1];
    const float* hf2    = (const float*)d_in[2];
    const float* conv_w = (const float*)d_in[3];
    const float* conv_b = (const float*)d_in[4];
    float* out = (float*)d_out;

    dim3 cb(32, 4);
    dim3 cg(HH / 4, NB, KSPLIT);            // (32,16,2) = 1024 CTAs
    conv_part_kernel<<<cg, cb>>>(fused, conv_w);

    dim3 ib(128, 2);
    dim3 ig(HH / 2, NB * 3);                // (64,48) = 3072 CTAs
    iwt2_kernel<<<ig, ib>>>(hf1, hf2, conv_b, out);
}